// round 10
// baseline (speedup 1.0000x reference)
#include <cuda_runtime.h>
#include <cuda_fp16.h>
#include <cstdint>

#define WSZ 7
#define NHD 8
#define HDIM 32
#define CDIM 256
#define HW 224
#define BATCH 4
#define NTOK (HW*HW)          // 50176
#define MTOT (BATCH*NTOK)     // 200704
#define N3 768                // 3*C
#define PAD 40                // gemm smem row stride (fp16): conflict-free for ldmatrix

// ---------------- scratch ----------------
__device__ __half g_wh[N3*CDIM];
__device__ float g_qkv[(size_t)MTOT*N3];
__device__ float g_bias[NHD*49*49];
__device__ int   g_src[1024*49];

// ---------------- w fp32 -> fp16 ----------------
__global__ void conv_w_kernel(const float2* __restrict__ w, int n2) {
    int i = blockIdx.x * blockDim.x + threadIdx.x;
    if (i >= n2) return;
    float2 v = w[i];
    reinterpret_cast<__half2*>(g_wh)[i] = __floats2half2_rn(v.x, v.y);
}

// ---------------- relative-position bias gather ----------------
__global__ void build_bias_kernel(const float* __restrict__ table) {
    int t = blockIdx.x * blockDim.x + threadIdx.x;
    if (t >= NHD * 49 * 49) return;
    int h = t / 2401;
    int r = t % 2401;
    int q = r / 49, k = r % 49;
    int qi = q / 7, qj = q % 7, ki = k / 7, kj = k % 7;
    int rel = (qi - ki + 6) * 13 + (qj - kj + 6);
    g_bias[t] = table[rel * NHD + h];
}

// ---------------- gather-row table ----------------
__global__ void build_src_kernel() {
    int t = blockIdx.x * blockDim.x + threadIdx.x;
    if (t >= 1024 * 49) return;
    int widx = t / 49, p = t % 49;
    int wy = widx >> 5, wx = widx & 31;
    int i = p / 7, j = p % 7;
    int sh = wy * 7 + i + 3; if (sh >= HW) sh -= HW;
    int sw = wx * 7 + j + 3; if (sw >= HW) sw -= HW;
    g_src[t] = sh * HW + sw;
}

// ---------------- helpers ----------------
__device__ __forceinline__ uint32_t s2u(const void* p) {
    return (uint32_t)__cvta_generic_to_shared(p);
}

#define LDSM4(R, ADDR)                                                          \
    asm volatile("ldmatrix.sync.aligned.m8n8.x4.shared.b16 {%0,%1,%2,%3}, [%4];" \
                 : "=r"((R)[0]), "=r"((R)[1]), "=r"((R)[2]), "=r"((R)[3])        \
                 : "r"(ADDR))

#define MMA16816F(D, A, B0, B1)                                                  \
    asm volatile(                                                                \
        "mma.sync.aligned.m16n8k16.row.col.f32.f16.f16.f32 "                     \
        "{%0,%1,%2,%3}, {%4,%5,%6,%7}, {%8,%9}, {%0,%1,%2,%3};\n"                \
        : "+f"((D)[0]), "+f"((D)[1]), "+f"((D)[2]), "+f"((D)[3])                 \
        : "r"((A)[0]), "r"((A)[1]), "r"((A)[2]), "r"((A)[3]), "r"(B0), "r"(B1))

// ---------------- QKV GEMM: 2-term fp16 split, warp tile 64x64 ----------------
// CTA 128(M) x 256(N), k-tile 32, 256 thr = 8 warps (2m x 4n), 1 CTA/SM.
// acc += xhi*wh + xlo*wh
__global__ __launch_bounds__(256, 1) void qkv_gemm_kernel(
        const float* __restrict__ x, const float* __restrict__ qkv_b) {
    __shared__ __half Ahi[128 * PAD];
    __shared__ __half Alo[128 * PAD];
    __shared__ __half Bh[256 * PAD];

    const int tid = threadIdx.x;
    const int lane = tid & 31;
    const int w = tid >> 5;
    const int wm = (w & 1) * 64;
    const int wn = (w >> 1) * 64;
    const int mbase = blockIdx.y * 128;
    const int nbase = blockIdx.x * 256;

    const int l8 = lane & 7;
    const int grp = lane >> 3;
    const int arow = l8 + (grp & 1) * 8;
    const int acol = (grp >> 1) * 8;

    // A staging: 2 threads per row (16 cols each); B staging: 1 thread per row (32 cols)
    const int sra = tid >> 1;
    const int sha = (tid & 1) * 16;
    const float* xbase = x + (size_t)(mbase + sra) * CDIM + sha;
    const __half* wbase = g_wh + (size_t)(nbase + tid) * CDIM;

    float acc[4][8][4];
#pragma unroll
    for (int mi = 0; mi < 4; ++mi)
#pragma unroll
        for (int nn = 0; nn < 8; ++nn)
#pragma unroll
            for (int e = 0; e < 4; ++e) acc[mi][nn][e] = 0.f;

    float4 a_st[4];
    uint4 b_st[4];

    {
        const float* ap = xbase;
        a_st[0] = *(const float4*)(ap);
        a_st[1] = *(const float4*)(ap + 4);
        a_st[2] = *(const float4*)(ap + 8);
        a_st[3] = *(const float4*)(ap + 12);
        b_st[0] = *(const uint4*)(wbase);
        b_st[1] = *(const uint4*)(wbase + 8);
        b_st[2] = *(const uint4*)(wbase + 16);
        b_st[3] = *(const uint4*)(wbase + 24);
    }

    for (int kt = 0; kt < 8; ++kt) {
        {
            __align__(16) __half hi[16];
            __align__(16) __half lo[16];
#pragma unroll
            for (int i = 0; i < 4; ++i) {
                float vv[4] = {a_st[i].x, a_st[i].y, a_st[i].z, a_st[i].w};
#pragma unroll
                for (int j = 0; j < 4; ++j) {
                    __half h = __float2half_rn(vv[j]);
                    hi[i * 4 + j] = h;
                    lo[i * 4 + j] = __float2half_rn(vv[j] - __half2float(h));
                }
            }
            *(uint4*)&Ahi[sra * PAD + sha] = *(const uint4*)&hi[0];
            *(uint4*)&Ahi[sra * PAD + sha + 8] = *(const uint4*)&hi[8];
            *(uint4*)&Alo[sra * PAD + sha] = *(const uint4*)&lo[0];
            *(uint4*)&Alo[sra * PAD + sha + 8] = *(const uint4*)&lo[8];
            *(uint4*)&Bh[tid * PAD + 0] = b_st[0];
            *(uint4*)&Bh[tid * PAD + 8] = b_st[1];
            *(uint4*)&Bh[tid * PAD + 16] = b_st[2];
            *(uint4*)&Bh[tid * PAD + 24] = b_st[3];
        }
        __syncthreads();

        if (kt < 7) {
            const float* ap = xbase + (kt + 1) * 32;
            a_st[0] = *(const float4*)(ap);
            a_st[1] = *(const float4*)(ap + 4);
            a_st[2] = *(const float4*)(ap + 8);
            a_st[3] = *(const float4*)(ap + 12);
            const __half* bp = wbase + (kt + 1) * 32;
            b_st[0] = *(const uint4*)(bp);
            b_st[1] = *(const uint4*)(bp + 8);
            b_st[2] = *(const uint4*)(bp + 16);
            b_st[3] = *(const uint4*)(bp + 24);
        }

#pragma unroll
        for (int kk = 0; kk < 32; kk += 16) {
            uint32_t ah[4][4], al[4][4], bh[8][2];
#pragma unroll
            for (int mi = 0; mi < 4; ++mi) {
                int off = (wm + mi * 16 + arow) * PAD + kk + acol;
                LDSM4(ah[mi], s2u(&Ahi[off]));
                LDSM4(al[mi], s2u(&Alo[off]));
            }
#pragma unroll
            for (int nj = 0; nj < 4; ++nj) {
                int off = (wn + nj * 16 + arow) * PAD + kk + acol;
                uint32_t r[4];
                LDSM4(r, s2u(&Bh[off]));
                bh[nj * 2][0] = r[0]; bh[nj * 2][1] = r[2];
                bh[nj * 2 + 1][0] = r[1]; bh[nj * 2 + 1][1] = r[3];
            }
#pragma unroll
            for (int mi = 0; mi < 4; ++mi)
#pragma unroll
                for (int nn = 0; nn < 8; ++nn) {
                    MMA16816F(acc[mi][nn], ah[mi], bh[nn][0], bh[nn][1]);
                    MMA16816F(acc[mi][nn], al[mi], bh[nn][0], bh[nn][1]);
                }
        }
        __syncthreads();
    }

    const int g = lane >> 2;
    const int tg = lane & 3;
#pragma unroll
    for (int mi = 0; mi < 4; ++mi)
#pragma unroll
        for (int nn = 0; nn < 8; ++nn) {
            int m0 = mbase + wm + mi * 16 + g;
            int n0 = nbase + wn + nn * 8 + tg * 2;
            float b0 = qkv_b[n0], b1 = qkv_b[n0 + 1];
            float2 v0 = make_float2(acc[mi][nn][0] + b0, acc[mi][nn][1] + b1);
            float2 v1 = make_float2(acc[mi][nn][2] + b0, acc[mi][nn][3] + b1);
            *reinterpret_cast<float2*>(&g_qkv[(size_t)m0 * N3 + n0]) = v0;
            *reinterpret_cast<float2*>(&g_qkv[(size_t)(m0 + 8) * N3 + n0]) = v1;
        }
}

// ---------------- windowed attention (unchanged from R9) ----------------
__global__ __launch_bounds__(224) void attn_kernel(const float* __restrict__ mask,
                                                   float* __restrict__ out) {
    __shared__ float qs[56][36];
    __shared__ float ksT[32][68];
    __shared__ float vs[52][36];
    __shared__ float S[56][68];

    const int tid = threadIdx.x;
    const int lane = tid & 31;
    const int w = tid >> 5;
    const int bid = blockIdx.x;
    const int head = bid & 7;
    const int win = bid >> 3;
    const int b = win >> 10;
    const int widx = win & 1023;
    const int* srcp = g_src + widx * 49;
    const size_t brow = (size_t)b * NTOK;

    for (int idx = tid; idx < 512; idx += 224) {
        int p = idx >> 3, d4 = (idx & 7) << 2;
        float4 q4 = make_float4(0.f, 0.f, 0.f, 0.f);
        float4 k4 = q4, v4 = q4;
        if (p < 49) {
            size_t row = brow + srcp[p];
            const float* base = g_qkv + row * N3 + head * HDIM + d4;
            q4 = *(const float4*)(base);
            k4 = *(const float4*)(base + 256);
            v4 = *(const float4*)(base + 512);
        }
        if (p < 56) *(float4*)&qs[p][d4] = q4;
        if (p < 52) *(float4*)&vs[p][d4] = v4;
        ksT[d4 + 0][p] = k4.x;
        ksT[d4 + 1][p] = k4.y;
        ksT[d4 + 2][p] = k4.z;
        ksT[d4 + 3][p] = k4.w;
    }
    __syncthreads();

    const float scale = 0.17677669529663687f;  // 32^-0.5
    const int qb = w * 8;

    {
        float acc[8][2];
#pragma unroll
        for (int r = 0; r < 8; ++r) { acc[r][0] = 0.f; acc[r][1] = 0.f; }

#pragma unroll
        for (int d = 0; d < 32; d += 4) {
            float k0[4], k1[4];
#pragma unroll
            for (int j = 0; j < 4; ++j) {
                k0[j] = ksT[d + j][lane];
                k1[j] = ksT[d + j][lane + 32];
            }
#pragma unroll
            for (int r = 0; r < 8; ++r) {
                float4 q4 = *(const float4*)&qs[qb + r][d];
                acc[r][0] += q4.x * k0[0] + q4.y * k0[1] + q4.z * k0[2] + q4.w * k0[3];
                acc[r][1] += q4.x * k1[0] + q4.y * k1[1] + q4.z * k1[2] + q4.w * k1[3];
            }
        }

        const int k1i = lane + 32;
#pragma unroll
        for (int r = 0; r < 8; ++r) {
            int qi = qb + r;
            if (qi < 49) {
                int bb = head * 2401 + qi * 49;
                size_t mm = (size_t)widx * 2401 + qi * 49;
                S[qi][lane] = acc[r][0] * scale + g_bias[bb + lane] + mask[mm + lane];
                if (k1i < 49)
                    S[qi][k1i] = acc[r][1] * scale + g_bias[bb + k1i] + mask[mm + k1i];
            }
        }
    }
    __syncthreads();

    for (int row = w; row < 49; row += 7) {
        float v0 = S[row][lane];
        float v1 = (lane + 32 < 49) ? S[row][lane + 32] : -1e30f;
        float m = fmaxf(v0, v1);
#pragma unroll
        for (int off = 16; off; off >>= 1) m = fmaxf(m, __shfl_xor_sync(0xffffffffu, m, off));
        float e0 = __expf(v0 - m);
        float e1 = (lane + 32 < 49) ? __expf(v1 - m) : 0.f;
        float s = e0 + e1;
#pragma unroll
        for (int off = 16; off; off >>= 1) s += __shfl_xor_sync(0xffffffffu, s, off);
        float inv = 1.f / s;
        S[row][lane] = e0 * inv;
        S[row][lane + 32] = e1 * inv;
    }
    __syncthreads();

    {
        float oacc[8];
#pragma unroll
        for (int r = 0; r < 8; ++r) oacc[r] = 0.f;

        for (int k = 0; k < 52; k += 4) {
            float vv[4];
#pragma unroll
            for (int j = 0; j < 4; ++j) vv[j] = vs[k + j][lane];
#pragma unroll
            for (int r = 0; r < 8; ++r) {
                if (qb + r < 49) {
                    float4 p4 = *(const float4*)&S[qb + r][k];
                    oacc[r] += p4.x * vv[0] + p4.y * vv[1] + p4.z * vv[2] + p4.w * vv[3];
                }
            }
        }

#pragma unroll
        for (int r = 0; r < 8; ++r) {
            int qi = qb + r;
            if (qi < 49) {
                size_t row = brow + srcp[qi];
                out[row * CDIM + head * HDIM + lane] = oacc[r];
            }
        }
    }
}

// ---------------- launch ----------------
extern "C" void kernel_launch(void* const* d_in, const int* in_sizes, int n_in,
                              void* d_out, int out_size) {
    const float* x     = (const float*)d_in[0];
    const float* mask  = (const float*)d_in[1];
    const float* qkv_w = (const float*)d_in[2];
    const float* qkv_b = (const float*)d_in[3];
    const float* table = (const float*)d_in[4];
    float* out = (float*)d_out;

    int nw2 = N3 * CDIM / 2;
    conv_w_kernel<<<(nw2 + 255) / 256, 256>>>((const float2*)qkv_w, nw2);
    build_bias_kernel<<<(NHD * 2401 + 255) / 256, 256>>>(table);
    build_src_kernel<<<(1024 * 49 + 255) / 256, 256>>>();

    dim3 gg(N3 / 256, MTOT / 128);  // (3, 1568)
    qkv_gemm_kernel<<<gg, 256>>>(x, qkv_b);

    attn_kernel<<<BATCH * 1024 * NHD, 224>>>(mask, out);
}